// round 6
// baseline (speedup 1.0000x reference)
#include <cuda_runtime.h>
#include <cuda_fp16.h>
#include <math.h>
#include <stdint.h>

#define BB 256
#define HH 1024
#define TT 128
#define FF 512

// GEMM tiling: CTA 64(M) x 128(N), KC=32 per stage, 4 stages, 256 threads (8 warps 2x4)
#define KC 32
#define NSTG 4
#define OFF_A  0
#define OFF_B  4096
#define STAGE_BYTES 12288
#define SMEM_TOTAL (NSTG * STAGE_BYTES)   // 49152

// ---------------- device scratch (static, no runtime alloc) ------------------
__device__ __half g_wsum[4096 * 1024];      // [n=4j+g][k] = (W+U)^T gate-interleaved
__device__ __half g_wcat[4096 * 2048];      // t=0: K = [W;U]
__device__ __half g_wd[512 * 1024];         // [f][k]
__device__ __half g_xcat[256 * 2048];       // [b][x0,h0]
__device__ __half g_xa[256 * 1024];         // ping
__device__ __half g_xb[256 * 1024];         // pong
__device__ __half g_seq[(size_t)BB * TT * HH];  // [b*T+t][k]
__device__ float g_c[BB * HH];

// ---------------- helpers -----------------------------------------------------
__device__ __forceinline__ uint32_t smem_u32(const void* p) {
    uint32_t a;
    asm("{ .reg .u64 t; cvta.to.shared.u64 t, %1; cvt.u32.u64 %0, t; }" : "=r"(a) : "l"(p));
    return a;
}
__device__ __forceinline__ uint32_t sw64(uint32_t o) { return o ^ ((o >> 3) & 0x30); }
__device__ __forceinline__ float sigm(float x) { return 1.0f / (1.0f + expf(-x)); }

#define CP_ASYNC16(sm, gp) \
    asm volatile("cp.async.cg.shared.global [%0], [%1], 16;" :: "r"(sm), "l"(gp) : "memory")
#define CP_COMMIT() asm volatile("cp.async.commit_group;" ::: "memory")
template <int N>
__device__ __forceinline__ void cp_wait() {
    asm volatile("cp.async.wait_group %0;" :: "n"(N) : "memory");
}

__device__ __forceinline__ void ldsm4(uint32_t* r, uint32_t addr) {
    asm volatile("ldmatrix.sync.aligned.m8n8.x4.shared.b16 {%0,%1,%2,%3}, [%4];"
                 : "=r"(r[0]), "=r"(r[1]), "=r"(r[2]), "=r"(r[3]) : "r"(addr));
}
__device__ __forceinline__ void mma16816(float* c, const uint32_t* a, uint32_t b0, uint32_t b1) {
    asm volatile("mma.sync.aligned.m16n8k16.row.col.f32.f16.f16.f32 "
                 "{%0,%1,%2,%3},{%4,%5,%6,%7},{%8,%9},{%0,%1,%2,%3};"
                 : "+f"(c[0]), "+f"(c[1]), "+f"(c[2]), "+f"(c[3])
                 : "r"(a[0]), "r"(a[1]), "r"(a[2]), "r"(a[3]), "r"(b0), "r"(b1));
}

// ---------------- pipelined GEMM mainloop ------------------------------------
// A[m][k] fp16, B[n][k] fp16, row-major, leading dim ldk. C += A*B^T.
__device__ __forceinline__ void issue_load(uint32_t sbase, int s, int c,
                                           const __half* A, int am0,
                                           const __half* B, int bn0, int ldk, int tid) {
    const uint32_t st = sbase + s * STAGE_BYTES;
    const int k0 = c * KC;
    const int ar = tid >> 2, ac = tid & 3;
    const size_t ga = (size_t)(am0 + ar) * ldk + k0 + ac * 8;
    const uint32_t sa = sw64((uint32_t)(ar * 64 + ac * 16));
    CP_ASYNC16(st + OFF_A + sa, A + ga);
#pragma unroll
    for (int it = 0; it < 2; ++it) {
        const int idx = it * 256 + tid;
        const int br = idx >> 2, bc = idx & 3;
        const size_t gb = (size_t)(bn0 + br) * ldk + k0 + bc * 8;
        const uint32_t sb = sw64((uint32_t)(br * 64 + bc * 16));
        CP_ASYNC16(st + OFF_B + sb, B + gb);
    }
    CP_COMMIT();
}

__device__ __forceinline__ void gemm_main(char* smem,
                                          const __half* A, int am0,
                                          const __half* B, int bn0, int ldk, int nch,
                                          float C[2][4][4]) {
    const uint32_t sbase = smem_u32(smem);
    const int tid = threadIdx.x;
    const int lane = tid & 31, wid = tid >> 5;
    const int wm = wid & 1, wn = wid >> 1;

    issue_load(sbase, 0, 0, A, am0, B, bn0, ldk, tid);
    issue_load(sbase, 1, 1, A, am0, B, bn0, ldk, tid);
    issue_load(sbase, 2, 2, A, am0, B, bn0, ldk, tid);

    const int lrow = lane & 15;
    const int lkb = (lane >> 4) * 16;

    for (int c = 0; c < nch; ++c) {
        const int s = c & (NSTG - 1);
        cp_wait<2>();
        __syncthreads();
        const uint32_t st = sbase + s * STAGE_BYTES;
#pragma unroll
        for (int h = 0; h < 2; ++h) {
            uint32_t ah[2][4], bh[2][4];
#pragma unroll
            for (int mi = 0; mi < 2; ++mi) {
                const uint32_t off = sw64((uint32_t)((wm * 32 + mi * 16 + lrow) * 64 + h * 32 + lkb));
                ldsm4(ah[mi], st + OFF_A + off);
            }
#pragma unroll
            for (int nj = 0; nj < 2; ++nj) {
                const uint32_t off = sw64((uint32_t)((wn * 32 + nj * 16 + lrow) * 64 + h * 32 + lkb));
                ldsm4(bh[nj], st + OFF_B + off);
            }
#pragma unroll
            for (int mi = 0; mi < 2; ++mi)
#pragma unroll
                for (int nt = 0; nt < 4; ++nt) {
                    const int gsel = nt >> 1, ssel = nt & 1;
                    mma16816(C[mi][nt], ah[mi], bh[gsel][ssel], bh[gsel][ssel + 2]);
                }
        }
        if (c + 3 < nch)
            issue_load(sbase, (c + 3) & (NSTG - 1), c + 3, A, am0, B, bn0, ldk, tid);
    }
}

// ---------------- fused LSTM step kernel --------------------------------------
// grid (32 n-tiles, 4 m-tiles), 256 threads. B rows gate-interleaved: n = 4*j + g.
__global__ __launch_bounds__(256)
void lstm_step_mma(const __half* __restrict__ A,
                   const __half* __restrict__ B, int ldk, int nch,
                   const float* __restrict__ bias, const float* __restrict__ c_in,
                   float* __restrict__ c_out,
                   __half* __restrict__ xnext, int t) {
    extern __shared__ char smem[];
    float C[2][4][4];
#pragma unroll
    for (int a = 0; a < 2; ++a)
#pragma unroll
        for (int bq = 0; bq < 4; ++bq)
#pragma unroll
            for (int d = 0; d < 4; ++d) C[a][bq][d] = 0.0f;

    const int am0 = blockIdx.y * 64;
    const int bn0 = blockIdx.x * 128;
    gemm_main(smem, A, am0, B, bn0, ldk, nch, C);

    const int lane = threadIdx.x & 31, wid = threadIdx.x >> 5;
    const int wm = wid & 1, wn = wid >> 1;
    const bool odd = lane & 1;

#pragma unroll
    for (int mi = 0; mi < 2; ++mi)
#pragma unroll
        for (int nt = 0; nt < 4; ++nt) {
            float* c = C[mi][nt];
            const float t0 = __shfl_xor_sync(0xFFFFFFFFu, c[0], 1);
            const float t1 = __shfl_xor_sync(0xFFFFFFFFu, c[1], 1);
            const float t2 = __shfl_xor_sync(0xFFFFFFFFu, c[2], 1);
            const float t3 = __shfl_xor_sync(0xFFFFFFFFu, c[3], 1);
            float zi, zf, zg, zo;
            int rofs;
            if (!odd) { zi = c[0]; zf = c[1]; zg = t0; zo = t1; rofs = 0; }
            else      { zi = t2;  zf = t3;  zg = c[2]; zo = c[3]; rofs = 8; }
            const int b = am0 + wm * 32 + mi * 16 + (lane >> 2) + rofs;
            const int nbase = bn0 + wn * 32 + nt * 8;
            const int j = (nbase >> 2) + ((lane & 3) >> 1);
            zi += bias[j];
            zf += bias[HH + j];
            zg += bias[2 * HH + j];
            zo += bias[3 * HH + j];
            const float cold = c_in[b * HH + j];
            const float cn = sigm(zf) * cold + sigm(zi) * tanhf(zg);
            const float hn = sigm(zo) * tanhf(cn);
            c_out[b * HH + j] = cn;
            const __half hh = __float2half(hn);
            xnext[b * HH + j] = hh;
            g_seq[((size_t)b * TT + t) * HH + j] = hh;
        }
}

// ---------------- dense emission ----------------------------------------------
// grid (4 n-tiles, 512 m-tiles): out[m][f] = seq[m] . wd[f] + bd[f]
__global__ __launch_bounds__(256)
void dense_mma(const float* __restrict__ bd, float* __restrict__ out) {
    extern __shared__ char smem[];
    float C[2][4][4];
#pragma unroll
    for (int a = 0; a < 2; ++a)
#pragma unroll
        for (int bq = 0; bq < 4; ++bq)
#pragma unroll
            for (int d = 0; d < 4; ++d) C[a][bq][d] = 0.0f;

    const int am0 = blockIdx.y * 64;
    const int bn0 = blockIdx.x * 128;
    gemm_main(smem, g_seq, am0, g_wd, bn0, HH, HH / KC, C);

    const int lane = threadIdx.x & 31, wid = threadIdx.x >> 5;
    const int wm = wid & 1, wn = wid >> 1;

#pragma unroll
    for (int mi = 0; mi < 2; ++mi)
#pragma unroll
        for (int nt = 0; nt < 4; ++nt) {
            const float* c = C[mi][nt];
            const int n = bn0 + wn * 32 + nt * 8 + 2 * (lane & 3);
            const int r = am0 + wm * 32 + mi * 16 + (lane >> 2);
            float2 v0 = {c[0] + bd[n], c[1] + bd[n + 1]};
            float2 v1 = {c[2] + bd[n], c[3] + bd[n + 1]};
            *reinterpret_cast<float2*>(out + (size_t)r * FF + n) = v0;
            *reinterpret_cast<float2*>(out + (size_t)(r + 8) * FF + n) = v1;
        }
}

// ---------------- prep kernels -------------------------------------------------
// wsum: out[n][k] with n = 4j+g, val = W[k][g*1024+j] + U[k][g*1024+j]
__global__ void prep_wsum(const float* __restrict__ W, const float* __restrict__ U) {
    __shared__ float tl[32][33];
    const int n0 = blockIdx.x * 32, k0 = blockIdx.y * 32;
    const int tx = threadIdx.x, ty = threadIdx.y;
    const int n = n0 + tx;
    const int col = ((n & 3) << 10) | (n >> 2);
    for (int kk = ty; kk < 32; kk += 8)
        tl[tx][kk] = W[(size_t)(k0 + kk) * 4096 + col] + U[(size_t)(k0 + kk) * 4096 + col];
    __syncthreads();
    for (int nn = ty; nn < 32; nn += 8)
        g_wsum[(size_t)(n0 + nn) * 1024 + k0 + tx] = __float2half(tl[nn][tx]);
}

// wcat: out[n][k2], k2<1024 -> W, else U
__global__ void prep_wcat(const float* __restrict__ W, const float* __restrict__ U) {
    __shared__ float tl[32][33];
    const int n0 = blockIdx.x * 32, k0 = blockIdx.y * 32;
    const int tx = threadIdx.x, ty = threadIdx.y;
    const int n = n0 + tx;
    const int col = ((n & 3) << 10) | (n >> 2);
    const float* S = (k0 < 1024) ? W : U;
    const int kbase = (k0 < 1024) ? k0 : (k0 - 1024);
    for (int kk = ty; kk < 32; kk += 8)
        tl[tx][kk] = S[(size_t)(kbase + kk) * 4096 + col];
    __syncthreads();
    for (int nn = ty; nn < 32; nn += 8)
        g_wcat[(size_t)(n0 + nn) * 2048 + k0 + tx] = __float2half(tl[nn][tx]);
}

// wd: out[f][k] = Wd[k][f]
__global__ void prep_wd(const float* __restrict__ Wd) {
    __shared__ float tl[32][33];
    const int n0 = blockIdx.x * 32, k0 = blockIdx.y * 32;
    const int tx = threadIdx.x, ty = threadIdx.y;
    for (int kk = ty; kk < 32; kk += 8)
        tl[tx][kk] = Wd[(size_t)(k0 + kk) * 512 + n0 + tx];
    __syncthreads();
    for (int nn = ty; nn < 32; nn += 8)
        g_wd[(size_t)(n0 + nn) * 1024 + k0 + tx] = __float2half(tl[nn][tx]);
}

// xcat: [256][2048] = [x0 | h0]
__global__ void prep_xc(const float* __restrict__ x0, const float* __restrict__ h0) {
    const int i = blockIdx.x * blockDim.x + threadIdx.x;
    const int m = i >> 11, k = i & 2047;
    const float v = (k < 1024) ? x0[m * 1024 + k] : h0[m * 1024 + k - 1024];
    g_xcat[i] = __float2half(v);
}

// ---------------- launch --------------------------------------------------------
extern "C" void kernel_launch(void* const* d_in, const int* in_sizes, int n_in,
                              void* d_out, int out_size) {
    const float* x0 = (const float*)d_in[0];
    const float* h0 = (const float*)d_in[1];
    const float* c0 = (const float*)d_in[2];
    const float* W  = (const float*)d_in[3];
    const float* U  = (const float*)d_in[4];
    const float* bi = (const float*)d_in[5];
    const float* Wd = (const float*)d_in[6];
    const float* bd = (const float*)d_in[7];
    float* out = (float*)d_out;

    static bool attr_done = false;
    if (!attr_done) {
        cudaFuncSetAttribute(lstm_step_mma, cudaFuncAttributeMaxDynamicSharedMemorySize, SMEM_TOTAL);
        cudaFuncSetAttribute(dense_mma, cudaFuncAttributeMaxDynamicSharedMemorySize, SMEM_TOTAL);
        attr_done = true;
    }

    void* p;
    cudaGetSymbolAddress(&p, g_wsum);  __half* wsum = (__half*)p;
    cudaGetSymbolAddress(&p, g_wcat);  __half* wcat = (__half*)p;
    cudaGetSymbolAddress(&p, g_xcat);  __half* xc   = (__half*)p;
    __half* xb[2];
    cudaGetSymbolAddress(&p, g_xa);    xb[0] = (__half*)p;
    cudaGetSymbolAddress(&p, g_xb);    xb[1] = (__half*)p;
    cudaGetSymbolAddress(&p, g_c);     float* cbuf = (float*)p;

    dim3 tb(32, 8);
    prep_wsum<<<dim3(128, 32), tb>>>(W, U);
    prep_wcat<<<dim3(128, 64), tb>>>(W, U);
    prep_wd<<<dim3(16, 32), tb>>>(Wd);
    prep_xc<<<2048, 256>>>(x0, h0);

    dim3 sgrid(32, 4);
    // t = 0: A = [x0,h0] (K=2048), B = [W;U]^T interleaved, c_in = c0, writes xb[0]
    lstm_step_mma<<<sgrid, 256, SMEM_TOTAL>>>(xc, wcat, 2048, 2048 / KC,
                                              bi, c0, cbuf, xb[0], 0);
    // t >= 1: A = h(t-1), B = (W+U)^T interleaved
    for (int t = 1; t < TT; ++t) {
        lstm_step_mma<<<sgrid, 256, SMEM_TOTAL>>>(xb[(t + 1) & 1], wsum, HH, HH / KC,
                                                  bi, cbuf, cbuf, xb[t & 1], t);
    }

    dense_mma<<<dim3(4, 512), 256, SMEM_TOTAL>>>(bd, out);
}